// round 5
// baseline (speedup 1.0000x reference)
#include <cuda_runtime.h>
#include <cuda_fp16.h>
#include <math.h>
#include <stdint.h>

#define B_  16
#define L_  4096
#define H_  512
#define NT_ 8
#define IN_ 10
#define OUT_ 1032
#define KP   1056            // padded K (66 chunks of 16)
#define NCH16 66
#define HH_ 256
#define NC_ 16
#define CH_ 256
#define EPS_ 1e-5f
#define NROW (B_*L_)
#define NTILE (NROW/64)

// ---------------- device scratch (static, allocation-free) ----------------
__device__ float g_xc[NROW*IN_];
__device__ float g_F [(size_t)NROW*KP];             // features (pads & skipped stay 0)
__device__ float g_W [4][H_][IN_];
__device__ float g_bias[4][H_];
__device__ float g_Ae[2][B_][NC_][H_];              // global-A chunk-entry states
__device__ float g_Lc[2][B_][NC_][H_];
__device__ float g_Se[2][B_][NC_][H_];
__device__ __half g_Gh[(size_t)NCH16*32*128];       // B fp16 fragment-major (pads 0)
__device__ float g_sv[HH_];
__device__ float g_cv[HH_];
__device__ int   g_tilef[NTILE];                    // per-64-row-tile nonzero flags

// ---------------- zero accumulators / flags --------------------------------
__global__ void k_zero() {
    int i = blockIdx.x*blockDim.x + threadIdx.x;
    if (i < 4*H_*IN_) ((float*)g_W)[i] = 0.f;
    if (i < 4*H_)     ((float*)g_bias)[i] = 0.f;
    if (i < HH_)      { g_sv[i] = 0.f; g_cv[i] = 0.f; }
    if (i < NTILE)    g_tilef[i] = 0;
}

// ---------------- fold gate weights through the 10-dim projection ----------
__global__ void k_fold(const float* __restrict__ fz, const float* __restrict__ fh,
                       const float* __restrict__ bz, const float* __restrict__ bh,
                       const float* __restrict__ fzb, const float* __restrict__ fhb,
                       const float* __restrict__ bzb, const float* __restrict__ bhb,
                       const float* __restrict__ fp, const float* __restrict__ fpb,
                       const float* __restrict__ bp, const float* __restrict__ bpb) {
    int p = blockIdx.x, sl = blockIdx.y;
    int h = threadIdx.x;
    const float* zw = (p==0)?fz:(p==1)?fh:(p==2)?bz:bh;
    const float* zb = (p==0)?fzb:(p==1)?fhb:(p==2)?bzb:bhb;
    const float* pw = (p<2)?fp:bp;
    const float* pb = (p<2)?fpb:bpb;
    float acc[IN_]; float ab = 0.f;
    #pragma unroll
    for (int i=0;i<IN_;i++) acc[i]=0.f;
    for (int d=sl*64; d<sl*64+64; d++) {
        float w = zw[h*H_+d];
        #pragma unroll
        for (int i=0;i<IN_;i++) acc[i] += w*pw[d*IN_+i];
        ab += w*pb[d];
    }
    #pragma unroll
    for (int i=0;i<IN_;i++) atomicAdd(&g_W[p][h][i], acc[i]);
    atomicAdd(&g_bias[p][h], ab + ((sl==0)? zb[h] : 0.f));
}

// ---------------- fold LN affine into gh_w1, emit fp16 fragment-major B ----
__global__ void k_prepG(const float* __restrict__ gw1, const float* __restrict__ gb1,
                        const float* __restrict__ lng, const float* __restrict__ lnb,
                        const float* __restrict__ tscp) {
    int k = threadIdx.x;                 // output col n, 0..255
    int j0 = blockIdx.x * (OUT_/8);
    float tsc = tscp[0];
    int nt = k >> 3, ng = k & 7;
    float s = 0.f, c = 0.f;
    for (int j=j0; j<j0+OUT_/8; j++) {
        float sc = (j >= OUT_-NT_) ? tsc : 1.0f;
        float w  = gw1[k*OUT_+j];
        __half Gh = __float2half_rn(lng[j]*sc*w);
        int kt = j >> 4, kin = j & 15;
        int lane = ng*4 + ((kin & 7) >> 1);
        int reg = kin >> 3, hs = kin & 1;
        g_Gh[(((size_t)(kt*32 + nt)*32 + lane)*2 + reg)*2 + hs] = Gh;
        s += __half2float(Gh);
        c += lnb[j]*sc*w;
    }
    atomicAdd(&g_sv[k], s);
    atomicAdd(&g_cv[k], c + ((blockIdx.x==0)? gb1[k] : 0.f));
}

// ---------------- time embedding + xc, te into F ---------------------------
__global__ void k_te(const float* __restrict__ x, const float* __restrict__ t,
                     const float* __restrict__ w1, const float* __restrict__ b1,
                     const float* __restrict__ w2, const float* __restrict__ b2) {
    int row = blockIdx.x*blockDim.x + threadIdx.x;
    if (row >= NROW) return;
    int b = row / L_;
    float ts = t[row] - t[b*L_];
    float r[NT_];
    #pragma unroll
    for (int j=0;j<NT_;j++) r[j] = fmaxf(ts*w1[j] + b1[j], 0.0f);
    #pragma unroll
    for (int k=0;k<NT_;k++) {
        float a = b2[k];
        #pragma unroll
        for (int j=0;j<NT_;j++) a += r[j]*w2[k*NT_+j];
        g_xc[row*IN_+2+k] = a;
        g_F[(size_t)row*KP + (OUT_-NT_) + k] = a;
    }
    g_xc[row*IN_+0] = x[row*2+0];
    g_xc[row*IN_+1] = x[row*2+1];
}

// fast sigmoid pieces
__device__ __forceinline__ void fsig(float arg, float& z, float& omz) {
    float e = __expf(-arg);
    z = __fdividef(1.0f, 1.0f + e);
    omz = e * z;
}

// ---------------- merged pass: global cumprod entry states (A + B1) --------
__global__ void k_scanAB1() {
    int b = blockIdx.x, dir = blockIdx.y;
    int h = threadIdx.x;
    __shared__ float xs[CH_][IN_];
    float wz[IN_]; float bz;
    int pz = dir*2;
    #pragma unroll
    for (int i=0;i<IN_;i++) wz[i] = g_W[pz][h][i];
    bz = g_bias[pz][h];
    float A = 1.0f;
    for (int cc=0; cc<NC_; cc++) {
        int c = dir ? (NC_-1-cc) : cc;
        g_Ae[dir][b][c][h] = A;
        int any = __syncthreads_or(A != 0.f);
        if (!any) {
            for (int cc2=cc+1; cc2<NC_; cc2++) {
                int c2 = dir ? (NC_-1-cc2) : cc2;
                g_Ae[dir][b][c2][h] = 0.f;
            }
            return;
        }
        const float* xcb = g_xc + ((size_t)b*L_ + (size_t)c*CH_)*IN_;
        for (int i=h; i<CH_*IN_; i+=H_) ((float*)xs)[i] = xcb[i];
        __syncthreads();
        int s0 = dir ? CH_-1 : 0;
        int ds = dir ? -1 : 1;
        for (int k=0;k<CH_;k++) {
            if (A == 0.f) break;
            int s = s0 + k*ds;
            float arg = bz;
            #pragma unroll
            for (int i=0;i<IN_;i++) arg += xs[s][i]*wz[i];
            float z, omz; fsig(arg, z, omz);
            A *= omz;
        }
        __syncthreads();
    }
}

// ---------------- scan pass C1: chunk local sums of d (skip dead chunks) ---
__global__ void k_scanC1() {
    int c = blockIdx.x, b = blockIdx.y, dir = blockIdx.z;
    int h = threadIdx.x;
    __shared__ float xs[CH_][IN_];
    float A = g_Ae[dir][b][c][h];
    int any = __syncthreads_or(A != 0.f);
    if (!any) { g_Lc[dir][b][c][h] = 0.f; return; }
    const float* xcb = g_xc + ((size_t)b*L_ + (size_t)c*CH_)*IN_;
    for (int i=h; i<CH_*IN_; i+=H_) ((float*)xs)[i] = xcb[i];
    float wz[IN_], wh[IN_]; float bz, bh;
    int pz = dir*2, ph = dir*2+1;
    #pragma unroll
    for (int i=0;i<IN_;i++) { wz[i]=g_W[pz][h][i]; wh[i]=g_W[ph][h][i]; }
    bz = g_bias[pz][h]; bh = g_bias[ph][h];
    __syncthreads();
    float Ls = 0.0f;
    int s0  = (dir==0)? 0 : CH_-1;
    int ds  = (dir==0)? 1 : -1;
    for (int k=0;k<CH_;k++) {
        if (A == 0.f) break;
        int s = s0 + k*ds;
        float az = bz, ah = bh;
        #pragma unroll
        for (int i=0;i<IN_;i++) { float xv = xs[s][i]; az += xv*wz[i]; ah += xv*wh[i]; }
        float z, omz; fsig(az, z, omz);
        A *= omz;
        Ls += __fdividef(z*ah, fmaxf(A, 1e-12f));
    }
    g_Lc[dir][b][c][h] = Ls;
}

// ---------------- scan pass B2: chunk-entry cumsum states ------------------
__global__ void k_scanB2() {
    int b = blockIdx.x, dir = blockIdx.y, h = threadIdx.x;
    float run = 0.0f;
    if (dir==0) { for (int c=0;c<NC_;c++)    { g_Se[0][b][c][h]=run; run += g_Lc[0][b][c][h]; } }
    else        { for (int c=NC_-1;c>=0;c--) { g_Se[1][b][c][h]=run; run += g_Lc[1][b][c][h]; } }
}

// ---------------- scan pass C2: emit shifted h = A*S, set tile flags -------
__global__ void k_scanC2() {
    int c = blockIdx.x, b = blockIdx.y, dir = blockIdx.z;
    int h = threadIdx.x;
    __shared__ float xs[CH_][IN_];
    float A = g_Ae[dir][b][c][h];
    int any = __syncthreads_or(A != 0.f);
    if (!any) return;                       // region stays exact 0 (static init)
    const float* xcb = g_xc + ((size_t)b*L_ + (size_t)c*CH_)*IN_;
    for (int i=h; i<CH_*IN_; i+=H_) ((float*)xs)[i] = xcb[i];
    float wz[IN_], wh[IN_]; float bz, bh;
    int pz = dir*2, ph = dir*2+1;
    #pragma unroll
    for (int i=0;i<IN_;i++) { wz[i]=g_W[pz][h][i]; wh[i]=g_W[ph][h][i]; }
    bz = g_bias[pz][h]; bh = g_bias[ph][h];
    float S = g_Se[dir][b][c][h];
    __syncthreads();
    int s0  = (dir==0)? 0 : CH_-1;
    int ds  = (dir==0)? 1 : -1;
    size_t fofs = (dir==0)? (size_t)h : (size_t)(H_ + h);
    int zstep = CH_;
    for (int k=0;k<CH_;k++) {
        if (A == 0.f) { zstep = k; break; }
        int s = s0 + k*ds;
        int l = c*CH_ + s;
        g_F[((size_t)(b*L_ + l))*KP + fofs] = A*S;   // state BEFORE consuming l
        float az = bz, ah = bh;
        #pragma unroll
        for (int i=0;i<IN_;i++) { float xv = xs[s][i]; az += xv*wz[i]; ah += xv*wh[i]; }
        float z, omz; fsig(az, z, omz);
        A *= omz;
        S += __fdividef(z*ah, fmaxf(A, 1e-12f));
    }
    // tile flags: fwd writes rows ascending from r0; bwd descending from r0+255
    int tile0 = (b*L_ + c*CH_) >> 6;
    #pragma unroll
    for (int ti=0; ti<4; ti++) {
        int thr = (dir==0) ? ti*64 : (192 - ti*64);
        int ta = __syncthreads_or(zstep > thr);
        if (ta && h == 0) atomicOr(&g_tilef[tile0 + ti], 1 << dir);
    }
}

// ---------------- fp16 mma GEMM (sparse-tile aware) + LN + gelu + w2 -------
#define GBM 64
__device__ __forceinline__ int chunk_of(int i, int flag, int nf) {
    if (i >= nf) return 64;              // te chunk (cols 1024..1039)
    if (flag == 2) return 32 + i;        // bwd only
    return i;                            // fwd-only or both (0..nf-1)
}

__global__ __launch_bounds__(512, 1) void k_gemm3(const float* __restrict__ w2,
                                                  const float* __restrict__ b2p,
                                                  float* __restrict__ out) {
    __shared__ float s_s[HH_], s_c[HH_], s_w2[HH_];
    __shared__ float s_sum[GBM], s_sq[GBM];
    __shared__ float s_mu[GBM], s_rs[GBM];
    __shared__ float s_part[GBM][4];

    int t = threadIdx.x;
    int lane = t & 31, warp = t >> 5;
    int wm = warp >> 2, wn = warp & 3;      // 4m x 4n warp grid
    int g  = lane >> 2, tig = lane & 3;
    int row0 = blockIdx.x * GBM;
    int r0 = row0 + wm*16 + g;

    if (t < HH_) { s_s[t] = g_sv[t]; s_c[t] = g_cv[t]; s_w2[t] = w2[t]; }

    int flag = g_tilef[blockIdx.x] & 3;
    int nf = ((flag & 1) ? 32 : 0) + ((flag & 2) ? 32 : 0);
    int total = nf + 1;

    float acc[8][4];
    #pragma unroll
    for (int i=0;i<8;i++) { acc[i][0]=0.f; acc[i][1]=0.f; acc[i][2]=0.f; acc[i][3]=0.f; }

    const float* Ar0 = g_F + (size_t)r0*KP     + tig*2;
    const float* Ar8 = Ar0 + 8*KP;
    const uint2* Bp  = ((const uint2*)g_Gh) + ((size_t)wn*8)*32 + lane;

    int ci = chunk_of(0, flag, nf);
    float2 fA0 = __ldg((const float2*)(Ar0 + ci*16));
    float2 fA1 = __ldg((const float2*)(Ar8 + ci*16));
    float2 fA2 = __ldg((const float2*)(Ar0 + ci*16 + 8));
    float2 fA3 = __ldg((const float2*)(Ar8 + ci*16 + 8));
    uint2 fB[8];
    {
        const uint2* Bn = Bp + (size_t)ci*1024;
        #pragma unroll
        for (int nt=0; nt<8; nt++) fB[nt] = __ldg(Bn + nt*32);
    }

    float ps0=0.f, pq0=0.f, ps1=0.f, pq1=0.f;

    for (int it=0; it<total; it++) {
        if (wn == 0) {
            ps0 += fA0.x+fA0.y+fA2.x+fA2.y;
            pq0 += fA0.x*fA0.x + fA0.y*fA0.y + fA2.x*fA2.x + fA2.y*fA2.y;
            ps1 += fA1.x+fA1.y+fA3.x+fA3.y;
            pq1 += fA1.x*fA1.x + fA1.y*fA1.y + fA3.x*fA3.x + fA3.y*fA3.y;
        }
        __half2 h0 = __floats2half2_rn(fA0.x, fA0.y);
        __half2 h1 = __floats2half2_rn(fA1.x, fA1.y);
        __half2 h2 = __floats2half2_rn(fA2.x, fA2.y);
        __half2 h3 = __floats2half2_rn(fA3.x, fA3.y);
        uint32_t a0 = *reinterpret_cast<uint32_t*>(&h0);
        uint32_t a1 = *reinterpret_cast<uint32_t*>(&h1);
        uint32_t a2 = *reinterpret_cast<uint32_t*>(&h2);
        uint32_t a3 = *reinterpret_cast<uint32_t*>(&h3);
        #pragma unroll
        for (int nt=0; nt<8; nt++) {
            asm volatile(
                "mma.sync.aligned.m16n8k16.row.col.f32.f16.f16.f32 "
                "{%0,%1,%2,%3}, {%4,%5,%6,%7}, {%8,%9}, {%0,%1,%2,%3};"
                : "+f"(acc[nt][0]), "+f"(acc[nt][1]), "+f"(acc[nt][2]), "+f"(acc[nt][3])
                : "r"(a0), "r"(a1), "r"(a2), "r"(a3), "r"(fB[nt].x), "r"(fB[nt].y));
        }
        if (it+1 < total) {
            ci = chunk_of(it+1, flag, nf);
            fA0 = __ldg((const float2*)(Ar0 + ci*16));
            fA1 = __ldg((const float2*)(Ar8 + ci*16));
            fA2 = __ldg((const float2*)(Ar0 + ci*16 + 8));
            fA3 = __ldg((const float2*)(Ar8 + ci*16 + 8));
            const uint2* Bn = Bp + (size_t)ci*1024;
            #pragma unroll
            for (int nt=0; nt<8; nt++) fB[nt] = __ldg(Bn + nt*32);
        }
    }

    if (wn == 0) {
        #pragma unroll
        for (int off=1; off<4; off<<=1) {
            ps0 += __shfl_xor_sync(0xffffffffu, ps0, off);
            pq0 += __shfl_xor_sync(0xffffffffu, pq0, off);
            ps1 += __shfl_xor_sync(0xffffffffu, ps1, off);
            pq1 += __shfl_xor_sync(0xffffffffu, pq1, off);
        }
        if (tig == 0) {
            s_sum[wm*16+g]   = ps0;  s_sq[wm*16+g]   = pq0;
            s_sum[wm*16+g+8] = ps1;  s_sq[wm*16+g+8] = pq1;
        }
    }
    __syncthreads();
    if (t < GBM) {
        float m = s_sum[t] * (1.0f/(float)OUT_);
        float v = s_sq[t]  * (1.0f/(float)OUT_) - m*m;
        s_mu[t] = m;
        s_rs[t] = rsqrtf(v + EPS_);
    }
    __syncthreads();

    float mu0 = s_mu[wm*16+g],   rs0 = s_rs[wm*16+g];
    float mu1 = s_mu[wm*16+g+8], rs1 = s_rs[wm*16+g+8];
    float po0 = 0.f, po1 = 0.f;
    #pragma unroll
    for (int nt=0; nt<8; nt++) {
        #pragma unroll
        for (int e=0; e<2; e++) {
            int col = wn*64 + nt*8 + tig*2 + e;
            float sS = s_s[col], sC = s_c[col], wv = s_w2[col];
            float v0 = (acc[nt][e]   - mu0*sS)*rs0 + sC;
            float v1 = (acc[nt][2+e] - mu1*sS)*rs1 + sC;
            float h0 = 0.5f*v0*(1.0f + erff(v0*0.70710678118654752440f));
            float h1 = 0.5f*v1*(1.0f + erff(v1*0.70710678118654752440f));
            po0 += h0*wv;
            po1 += h1*wv;
        }
    }
    #pragma unroll
    for (int off=1; off<4; off<<=1) {
        po0 += __shfl_xor_sync(0xffffffffu, po0, off);
        po1 += __shfl_xor_sync(0xffffffffu, po1, off);
    }
    if (tig == 0) {
        s_part[wm*16+g][wn]   = po0;
        s_part[wm*16+g+8][wn] = po1;
    }
    __syncthreads();
    if (t < GBM) {
        out[row0 + t] = b2p[0] + s_part[t][0] + s_part[t][1] + s_part[t][2] + s_part[t][3];
    }
}

// ---------------- launch ---------------------------------------------------
extern "C" void kernel_launch(void* const* d_in, const int* in_sizes, int n_in,
                              void* d_out, int out_size) {
    const float* x      = (const float*)d_in[0];
    const float* t      = (const float*)d_in[1];
    const float* te_w1  = (const float*)d_in[2];
    const float* te_b1  = (const float*)d_in[3];
    const float* te_w2  = (const float*)d_in[4];
    const float* te_b2  = (const float*)d_in[5];
    const float* fproj_w= (const float*)d_in[6];
    const float* fproj_b= (const float*)d_in[7];
    const float* bproj_w= (const float*)d_in[8];
    const float* bproj_b= (const float*)d_in[9];
    const float* fz_w   = (const float*)d_in[10];
    const float* fz_b   = (const float*)d_in[11];
    const float* fh_w   = (const float*)d_in[12];
    const float* fh_b   = (const float*)d_in[13];
    const float* bz_w   = (const float*)d_in[14];
    const float* bz_b   = (const float*)d_in[15];
    const float* bh_w   = (const float*)d_in[16];
    const float* bh_b   = (const float*)d_in[17];
    const float* ln_g   = (const float*)d_in[18];
    const float* ln_b   = (const float*)d_in[19];
    const float* tsc    = (const float*)d_in[20];
    const float* gh_w1  = (const float*)d_in[21];
    const float* gh_b1  = (const float*)d_in[22];
    const float* gh_w2  = (const float*)d_in[23];
    const float* gh_b2  = (const float*)d_in[24];
    float* out = (float*)d_out;

    k_zero<<<(4*H_*IN_ + 255)/256, 256>>>();
    k_fold<<<dim3(4, 8), H_>>>(fz_w, fh_w, bz_w, bh_w, fz_b, fh_b, bz_b, bh_b,
                               fproj_w, fproj_b, bproj_w, bproj_b);
    k_prepG<<<8, HH_>>>(gh_w1, gh_b1, ln_g, ln_b, tsc);
    k_te<<<NROW/256, 256>>>(x, t, te_w1, te_b1, te_w2, te_b2);
    k_scanAB1<<<dim3(B_, 2), H_>>>();
    k_scanC1<<<dim3(NC_, B_, 2), H_>>>();
    k_scanB2<<<dim3(B_, 2), H_>>>();
    k_scanC2<<<dim3(NC_, B_, 2), H_>>>();
    k_gemm3<<<NROW/GBM, 512>>>(gh_w2, gh_b2, out);
}

// round 6
// speedup vs baseline: 3.4201x; 3.4201x over previous
#include <cuda_runtime.h>
#include <cuda_fp16.h>
#include <math.h>
#include <stdint.h>

#define B_  16
#define L_  4096
#define H_  512
#define NT_ 8
#define IN_ 10
#define OUT_ 1032
#define KP   1056            // padded K (66 chunks of 16)
#define NCH16 66
#define HH_ 256
#define NC_ 16
#define CH_ 256
#define EPS_ 1e-5f
#define NROW (B_*L_)
#define NTILE (NROW/64)

// ---------------- device scratch (static, allocation-free) ----------------
__device__ float g_xc[NROW*IN_];
__device__ float g_F [(size_t)NROW*KP];             // features (dead regions stay 0)
__device__ float g_W [4][H_][IN_];
__device__ float g_bias[4][H_];
__device__ float g_P [2][B_][NC_][H_];
__device__ float g_Ae[2][B_][NC_][H_];
__device__ float g_Lc[2][B_][NC_][H_];
__device__ float g_Se[2][B_][NC_][H_];
__device__ __half g_Gh[(size_t)NCH16*32*128];       // B fp16 fragment-major (pads 0)
__device__ float g_sv[HH_];
__device__ float g_cv[HH_];
__device__ int   g_tilef[NTILE];                    // per-64-row-tile nonzero flags

// ---------------- zero accumulators / flags --------------------------------
__global__ void k_zero() {
    int i = blockIdx.x*blockDim.x + threadIdx.x;
    if (i < 4*H_*IN_) ((float*)g_W)[i] = 0.f;
    if (i < 4*H_)     ((float*)g_bias)[i] = 0.f;
    if (i < HH_)      { g_sv[i] = 0.f; g_cv[i] = 0.f; }
    if (i < NTILE)    g_tilef[i] = 0;
}

// ---------------- fold gate weights through the 10-dim projection ----------
__global__ void k_fold(const float* __restrict__ fz, const float* __restrict__ fh,
                       const float* __restrict__ bz, const float* __restrict__ bh,
                       const float* __restrict__ fzb, const float* __restrict__ fhb,
                       const float* __restrict__ bzb, const float* __restrict__ bhb,
                       const float* __restrict__ fp, const float* __restrict__ fpb,
                       const float* __restrict__ bp, const float* __restrict__ bpb) {
    int p = blockIdx.x, sl = blockIdx.y;
    int h = threadIdx.x;
    const float* zw = (p==0)?fz:(p==1)?fh:(p==2)?bz:bh;
    const float* zb = (p==0)?fzb:(p==1)?fhb:(p==2)?bzb:bhb;
    const float* pw = (p<2)?fp:bp;
    const float* pb = (p<2)?fpb:bpb;
    float acc[IN_]; float ab = 0.f;
    #pragma unroll
    for (int i=0;i<IN_;i++) acc[i]=0.f;
    for (int d=sl*64; d<sl*64+64; d++) {
        float w = zw[h*H_+d];
        #pragma unroll
        for (int i=0;i<IN_;i++) acc[i] += w*pw[d*IN_+i];
        ab += w*pb[d];
    }
    #pragma unroll
    for (int i=0;i<IN_;i++) atomicAdd(&g_W[p][h][i], acc[i]);
    atomicAdd(&g_bias[p][h], ab + ((sl==0)? zb[h] : 0.f));
}

// ---------------- fold LN affine into gh_w1, emit fp16 fragment-major B ----
__global__ void k_prepG(const float* __restrict__ gw1, const float* __restrict__ gb1,
                        const float* __restrict__ lng, const float* __restrict__ lnb,
                        const float* __restrict__ tscp) {
    int k = threadIdx.x;                 // output col n, 0..255
    int j0 = blockIdx.x * (OUT_/8);
    float tsc = tscp[0];
    int nt = k >> 3, ng = k & 7;
    float s = 0.f, c = 0.f;
    for (int j=j0; j<j0+OUT_/8; j++) {
        float sc = (j >= OUT_-NT_) ? tsc : 1.0f;
        float w  = gw1[k*OUT_+j];
        __half Gh = __float2half_rn(lng[j]*sc*w);
        int kt = j >> 4, kin = j & 15;
        int lane = ng*4 + ((kin & 7) >> 1);
        int reg = kin >> 3, hs = kin & 1;
        g_Gh[(((size_t)(kt*32 + nt)*32 + lane)*2 + reg)*2 + hs] = Gh;
        s += __half2float(Gh);
        c += lnb[j]*sc*w;
    }
    atomicAdd(&g_sv[k], s);
    atomicAdd(&g_cv[k], c + ((blockIdx.x==0)? gb1[k] : 0.f));
}

// ---------------- time embedding + xc, te into F ---------------------------
__global__ void k_te(const float* __restrict__ x, const float* __restrict__ t,
                     const float* __restrict__ w1, const float* __restrict__ b1,
                     const float* __restrict__ w2, const float* __restrict__ b2) {
    int row = blockIdx.x*blockDim.x + threadIdx.x;
    if (row >= NROW) return;
    int b = row / L_;
    float ts = t[row] - t[b*L_];
    float r[NT_];
    #pragma unroll
    for (int j=0;j<NT_;j++) r[j] = fmaxf(ts*w1[j] + b1[j], 0.0f);
    #pragma unroll
    for (int k=0;k<NT_;k++) {
        float a = b2[k];
        #pragma unroll
        for (int j=0;j<NT_;j++) a += r[j]*w2[k*NT_+j];
        g_xc[row*IN_+2+k] = a;
        g_F[(size_t)row*KP + (OUT_-NT_) + k] = a;
    }
    g_xc[row*IN_+0] = x[row*2+0];
    g_xc[row*IN_+1] = x[row*2+1];
}

// fast sigmoid pieces
__device__ __forceinline__ void fsig(float arg, float& z, float& omz) {
    float e = __expf(-arg);
    z = __fdividef(1.0f, 1.0f + e);
    omz = e * z;
}

// ---------------- scan pass A: chunk-local a-products (dense, R4) ----------
__global__ void k_scanA() {
    int c = blockIdx.x, b = blockIdx.y, dir = blockIdx.z;
    int h = threadIdx.x;
    __shared__ float xs[CH_][IN_];
    const float* xcb = g_xc + ((size_t)b*L_ + (size_t)c*CH_)*IN_;
    for (int i=h; i<CH_*IN_; i+=H_) ((float*)xs)[i] = xcb[i];
    float wz[IN_]; float bz;
    int pz = dir*2;
    #pragma unroll
    for (int i=0;i<IN_;i++) wz[i] = g_W[pz][h][i];
    bz = g_bias[pz][h];
    __syncthreads();
    float A = 1.0f;
    int s0 = (dir==0)? 0 : CH_-1;
    int ds = (dir==0)? 1 : -1;
    #pragma unroll 4
    for (int k=0;k<CH_;k++) {
        int s = s0 + k*ds;
        float arg = bz;
        #pragma unroll
        for (int i=0;i<IN_;i++) arg += xs[s][i]*wz[i];
        float z, omz; fsig(arg, z, omz);
        A *= omz;
    }
    g_P[dir][b][c][h] = A;
}

// ---------------- scan pass B1: chunk-entry cumprod states (R4) ------------
__global__ void k_scanB1() {
    int b = blockIdx.x, dir = blockIdx.y, h = threadIdx.x;
    float run = 1.0f;
    if (dir==0) { for (int c=0;c<NC_;c++)    { g_Ae[0][b][c][h]=run; run *= g_P[0][b][c][h]; } }
    else        { for (int c=NC_-1;c>=0;c--) { g_Ae[1][b][c][h]=run; run *= g_P[1][b][c][h]; } }
}

// ---------------- scan pass C1: chunk local sums (R4 body + block skip) ----
__global__ void k_scanC1() {
    int c = blockIdx.x, b = blockIdx.y, dir = blockIdx.z;
    int h = threadIdx.x;
    __shared__ float xs[CH_][IN_];
    float A = g_Ae[dir][b][c][h];
    if (!__syncthreads_or(A != 0.f)) { g_Lc[dir][b][c][h] = 0.f; return; }
    const float* xcb = g_xc + ((size_t)b*L_ + (size_t)c*CH_)*IN_;
    for (int i=h; i<CH_*IN_; i+=H_) ((float*)xs)[i] = xcb[i];
    float wz[IN_], wh[IN_]; float bz, bh;
    int pz = dir*2, ph = dir*2+1;
    #pragma unroll
    for (int i=0;i<IN_;i++) { wz[i]=g_W[pz][h][i]; wh[i]=g_W[ph][h][i]; }
    bz = g_bias[pz][h]; bh = g_bias[ph][h];
    __syncthreads();
    float Ls = 0.0f;
    int s0  = (dir==0)? 0 : CH_-1;
    int ds  = (dir==0)? 1 : -1;
    #pragma unroll 4
    for (int k=0;k<CH_;k++) {
        int s = s0 + k*ds;
        float az = bz, ah = bh;
        #pragma unroll
        for (int i=0;i<IN_;i++) { float xv = xs[s][i]; az += xv*wz[i]; ah += xv*wh[i]; }
        float z, omz; fsig(az, z, omz);
        A *= omz;
        Ls += __fdividef(z*ah, fmaxf(A, 1e-12f));
    }
    g_Lc[dir][b][c][h] = Ls;
}

// ---------------- scan pass B2: chunk-entry cumsum states (R4) -------------
__global__ void k_scanB2() {
    int b = blockIdx.x, dir = blockIdx.y, h = threadIdx.x;
    float run = 0.0f;
    if (dir==0) { for (int c=0;c<NC_;c++)    { g_Se[0][b][c][h]=run; run += g_Lc[0][b][c][h]; } }
    else        { for (int c=NC_-1;c>=0;c--) { g_Se[1][b][c][h]=run; run += g_Lc[1][b][c][h]; } }
}

// ---------------- scan pass C2: emit h = A*S (R4 body + skip + flags) ------
__global__ void k_scanC2() {
    int c = blockIdx.x, b = blockIdx.y, dir = blockIdx.z;
    int h = threadIdx.x;
    __shared__ float xs[CH_][IN_];
    float A = g_Ae[dir][b][c][h];
    if (!__syncthreads_or(A != 0.f)) return;    // region stays exact 0
    const float* xcb = g_xc + ((size_t)b*L_ + (size_t)c*CH_)*IN_;
    for (int i=h; i<CH_*IN_; i+=H_) ((float*)xs)[i] = xcb[i];
    float wz[IN_], wh[IN_]; float bz, bh;
    int pz = dir*2, ph = dir*2+1;
    #pragma unroll
    for (int i=0;i<IN_;i++) { wz[i]=g_W[pz][h][i]; wh[i]=g_W[ph][h][i]; }
    bz = g_bias[pz][h]; bh = g_bias[ph][h];
    float S = g_Se[dir][b][c][h];
    __syncthreads();
    int s0  = (dir==0)? 0 : CH_-1;
    int ds  = (dir==0)? 1 : -1;
    size_t fofs = (dir==0)? (size_t)h : (size_t)(H_ + h);
    int zstep = 0;
    #pragma unroll 4
    for (int k=0;k<CH_;k++) {
        int s = s0 + k*ds;
        int l = c*CH_ + s;
        if (A != 0.f) zstep = k+1;              // predicated select, no branch
        g_F[((size_t)(b*L_ + l))*KP + fofs] = A*S;   // state BEFORE consuming l
        float az = bz, ah = bh;
        #pragma unroll
        for (int i=0;i<IN_;i++) { float xv = xs[s][i]; az += xv*wz[i]; ah += xv*wh[i]; }
        float z, omz; fsig(az, z, omz);
        A *= omz;
        S += __fdividef(z*ah, fmaxf(A, 1e-12f));
    }
    // tile flags: fwd writes ascending from chunk start; bwd descending from end
    int tile0 = (b*L_ + c*CH_) >> 6;
    #pragma unroll
    for (int ti=0; ti<4; ti++) {
        int thr = (dir==0) ? ti*64 : (192 - ti*64);
        int ta = __syncthreads_or(zstep > thr);
        if (ta && h == 0) atomicOr(&g_tilef[tile0 + ti], 1 << dir);
    }
}

// ---------------- fp16 mma GEMM (R4 body, contiguous live range) -----------
#define GBM 64
__global__ __launch_bounds__(512, 1) void k_gemm3(const float* __restrict__ w2,
                                                  const float* __restrict__ b2p,
                                                  float* __restrict__ out) {
    __shared__ float s_s[HH_], s_c[HH_], s_w2[HH_];
    __shared__ float s_sum[GBM], s_sq[GBM];
    __shared__ float s_mu[GBM], s_rs[GBM];
    __shared__ float s_part[GBM][4];

    int t = threadIdx.x;
    int lane = t & 31, warp = t >> 5;
    int wm = warp >> 2, wn = warp & 3;      // 4m x 4n warp grid
    int g  = lane >> 2, tig = lane & 3;
    int row0 = blockIdx.x * GBM;
    int r0 = row0 + wm*16 + g;

    if (t < HH_) { s_s[t] = g_sv[t]; s_c[t] = g_cv[t]; s_w2[t] = w2[t]; }

    int flag = g_tilef[blockIdx.x] & 3;
    int c0 = (flag & 1) ? 0 : 32;           // contiguous live chunk range start
    int n  = (flag == 3) ? 64 : (flag ? 32 : 0);
    int total = n + 1;                      // + te chunk (64)

    float acc[8][4];
    #pragma unroll
    for (int i=0;i<8;i++) { acc[i][0]=0.f; acc[i][1]=0.f; acc[i][2]=0.f; acc[i][3]=0.f; }

    const float* Ar0 = g_F + (size_t)r0*KP     + tig*2;
    const float* Ar8 = Ar0 + 8*KP;
    const uint2* Bp  = ((const uint2*)g_Gh) + ((size_t)wn*8)*32 + lane;

    int ci = (0 < n) ? c0 : 64;
    float2 fA0 = __ldg((const float2*)(Ar0 + ci*16));
    float2 fA1 = __ldg((const float2*)(Ar8 + ci*16));
    float2 fA2 = __ldg((const float2*)(Ar0 + ci*16 + 8));
    float2 fA3 = __ldg((const float2*)(Ar8 + ci*16 + 8));
    uint2 fB[8];
    {
        const uint2* Bn = Bp + (size_t)ci*1024;
        #pragma unroll
        for (int nt=0; nt<8; nt++) fB[nt] = __ldg(Bn + nt*32);
    }

    float ps0=0.f, pq0=0.f, ps1=0.f, pq1=0.f;

    for (int it=0; it<total; it++) {
        if (wn == 0) {
            ps0 += fA0.x+fA0.y+fA2.x+fA2.y;
            pq0 += fA0.x*fA0.x + fA0.y*fA0.y + fA2.x*fA2.x + fA2.y*fA2.y;
            ps1 += fA1.x+fA1.y+fA3.x+fA3.y;
            pq1 += fA1.x*fA1.x + fA1.y*fA1.y + fA3.x*fA3.x + fA3.y*fA3.y;
        }
        __half2 h0 = __floats2half2_rn(fA0.x, fA0.y);
        __half2 h1 = __floats2half2_rn(fA1.x, fA1.y);
        __half2 h2 = __floats2half2_rn(fA2.x, fA2.y);
        __half2 h3 = __floats2half2_rn(fA3.x, fA3.y);
        uint32_t a0 = *reinterpret_cast<uint32_t*>(&h0);
        uint32_t a1 = *reinterpret_cast<uint32_t*>(&h1);
        uint32_t a2 = *reinterpret_cast<uint32_t*>(&h2);
        uint32_t a3 = *reinterpret_cast<uint32_t*>(&h3);
        #pragma unroll
        for (int nt=0; nt<8; nt++) {
            asm volatile(
                "mma.sync.aligned.m16n8k16.row.col.f32.f16.f16.f32 "
                "{%0,%1,%2,%3}, {%4,%5,%6,%7}, {%8,%9}, {%0,%1,%2,%3};"
                : "+f"(acc[nt][0]), "+f"(acc[nt][1]), "+f"(acc[nt][2]), "+f"(acc[nt][3])
                : "r"(a0), "r"(a1), "r"(a2), "r"(a3), "r"(fB[nt].x), "r"(fB[nt].y));
        }
        if (it+1 < total) {
            int itn = it+1;
            ci = (itn < n) ? (c0 + itn) : 64;   // branchless select
            fA0 = __ldg((const float2*)(Ar0 + ci*16));
            fA1 = __ldg((const float2*)(Ar8 + ci*16));
            fA2 = __ldg((const float2*)(Ar0 + ci*16 + 8));
            fA3 = __ldg((const float2*)(Ar8 + ci*16 + 8));
            const uint2* Bn = Bp + (size_t)ci*1024;
            #pragma unroll
            for (int nt=0; nt<8; nt++) fB[nt] = __ldg(Bn + nt*32);
        }
    }

    if (wn == 0) {
        #pragma unroll
        for (int off=1; off<4; off<<=1) {
            ps0 += __shfl_xor_sync(0xffffffffu, ps0, off);
            pq0 += __shfl_xor_sync(0xffffffffu, pq0, off);
            ps1 += __shfl_xor_sync(0xffffffffu, ps1, off);
            pq1 += __shfl_xor_sync(0xffffffffu, pq1, off);
        }
        if (tig == 0) {
            s_sum[wm*16+g]   = ps0;  s_sq[wm*16+g]   = pq0;
            s_sum[wm*16+g+8] = ps1;  s_sq[wm*16+g+8] = pq1;
        }
    }
    __syncthreads();
    if (t < GBM) {
        float m = s_sum[t] * (1.0f/(float)OUT_);
        float v = s_sq[t]  * (1.0f/(float)OUT_) - m*m;
        s_mu[t] = m;
        s_rs[t] = rsqrtf(v + EPS_);
    }
    __syncthreads();

    float mu0 = s_mu[wm*16+g],   rs0 = s_rs[wm*16+g];
    float mu1 = s_mu[wm*16+g+8], rs1 = s_rs[wm*16+g+8];
    float po0 = 0.f, po1 = 0.f;
    #pragma unroll
    for (int nt=0; nt<8; nt++) {
        #pragma unroll
        for (int e=0; e<2; e++) {
            int col = wn*64 + nt*8 + tig*2 + e;
            float sS = s_s[col], sC = s_c[col], wv = s_w2[col];
            float v0 = (acc[nt][e]   - mu0*sS)*rs0 + sC;
            float v1 = (acc[nt][2+e] - mu1*sS)*rs1 + sC;
            float h0 = 0.5f*v0*(1.0f + erff(v0*0.70710678118654752440f));
            float h1 = 0.5f*v1*(1.0f + erff(v1*0.70710678118654752440f));
            po0 += h0*wv;
            po1 += h1*wv;
        }
    }
    #pragma unroll
    for (int off=1; off<4; off<<=1) {
        po0 += __shfl_xor_sync(0xffffffffu, po0, off);
        po1 += __shfl_xor_sync(0xffffffffu, po1, off);
    }
    if (tig == 0) {
        s_part[wm*16+g][wn]   = po0;
        s_part[wm*16+g+8][wn] = po1;
    }
    __syncthreads();
    if (t < GBM) {
        out[row0 + t] = b2p[0] + s_part[t][0] + s_part[t][1] + s_part[t][2] + s_part[t][3];
    }
}

// ---------------- launch ---------------------------------------------------
extern "C" void kernel_launch(void* const* d_in, const int* in_sizes, int n_in,
                              void* d_out, int out_size) {
    const float* x      = (const float*)d_in[0];
    const float* t      = (const float*)d_in[1];
    const float* te_w1  = (const float*)d_in[2];
    const float* te_b1  = (const float*)d_in[3];
    const float* te_w2  = (const float*)d_in[4];
    const float* te_b2  = (const float*)d_in[5];
    const float* fproj_w= (const float*)d_in[6];
    const float* fproj_b= (const float*)d_in[7];
    const float* bproj_w= (const float*)d_in[8];
    const float* bproj_b= (const float*)d_in[9];
    const float* fz_w   = (const float*)d_in[10];
    const float* fz_b   = (const float*)d_in[11];
    const float* fh_w   = (const float*)d_in[12];
    const float* fh_b   = (const float*)d_in[13];
    const float* bz_w   = (const float*)d_in[14];
    const float* bz_b   = (const float*)d_in[15];
    const float* bh_w   = (const float*)d_in[16];
    const float* bh_b   = (const float*)d_in[17];
    const float* ln_g   = (const float*)d_in[18];
    const float* ln_b   = (const float*)d_in[19];
    const float* tsc    = (const float*)d_in[20];
    const float* gh_w1  = (const float*)d_in[21];
    const float* gh_b1  = (const float*)d_in[22];
    const float* gh_w2  = (const float*)d_in[23];
    const float* gh_b2  = (const float*)d_in[24];
    float* out = (float*)d_out;

    k_zero<<<(4*H_*IN_ + 255)/256, 256>>>();
    k_fold<<<dim3(4, 8), H_>>>(fz_w, fh_w, bz_w, bh_w, fz_b, fh_b, bz_b, bh_b,
                               fproj_w, fproj_b, bproj_w, bproj_b);
    k_prepG<<<8, HH_>>>(gh_w1, gh_b1, ln_g, ln_b, tsc);
    k_te<<<NROW/256, 256>>>(x, t, te_w1, te_b1, te_w2, te_b2);
    k_scanA <<<dim3(NC_, B_, 2), H_>>>();
    k_scanB1<<<dim3(B_, 2), H_>>>();
    k_scanC1<<<dim3(NC_, B_, 2), H_>>>();
    k_scanB2<<<dim3(B_, 2), H_>>>();
    k_scanC2<<<dim3(NC_, B_, 2), H_>>>();
    k_gemm3<<<NROW/GBM, 512>>>(gh_w2, gh_b2, out);
}